// round 9
// baseline (speedup 1.0000x reference)
#include <cuda_runtime.h>

// XY model log-density: out[s] = sum_i cos(x[up(i)] - x[i]) + cos(x[right(i)] - x[i])
// 64x64 lattice (4096 sites), 16384 samples, BETA = 1.
//
// R9: each warp owns 32 consecutive float4 chunks (= 2 lattice rows).
// Up-neighbors for lanes 0-15 come from lane+16's registers (shfl_down 16);
// only lanes 16-31 load the b-chunk from memory (predicated, coalesced).
// -25% total L1/L2 request traffic; DRAM unique bytes unchanged.

#define LATTICE 4096
#define THREADS 256

// FMA-pipe cos for d in (-2pi,2pi): half-angle + even Taylor, err <= 4e-6.
__device__ __forceinline__ float cos_poly(float d)
{
    const float y = 0.5f * d;
    const float u = y * y;
    float p = -1.1470746e-11f;
    p = fmaf(p, u,  2.0876757e-9f);
    p = fmaf(p, u, -2.7557319e-7f);
    p = fmaf(p, u,  2.4801587e-5f);
    p = fmaf(p, u, -1.3888889e-3f);
    p = fmaf(p, u,  4.1666668e-2f);
    p = fmaf(p, u, -0.5f);
    p = fmaf(p, u,  1.0f);              // p = cos(y)
    return fmaf(p + p, p, -1.0f);       // 2p^2 - 1
}

__global__ __launch_bounds__(THREADS) void xy_hamiltonian_kernel(
    const float* __restrict__ state,
    float* __restrict__ out)
{
    __shared__ float warp_sums[THREADS / 32];

    const int tid  = threadIdx.x;
    const int wid  = tid >> 5;
    const int lane = tid & 31;
    const float4* __restrict__ rp4 =
        reinterpret_cast<const float4*>(state + (size_t)blockIdx.x * LATTICE);

    // Right-neighbor source lane: lanes 0-15 cover one lattice row, lanes
    // 16-31 the next; boundary right-neighbor wraps within the 16-lane group.
    const int src_lane = (lane & ~15) | ((lane + 1) & 15);
    const bool hi_half = (lane >= 16);

    float acc  = 0.0f;
    float accp = 0.0f;
    #pragma unroll
    for (int k = 0; k < 4; k++) {
        // Warp (wid + 8k) covers chunks [(wid+8k)*32, +32): 2 lattice rows.
        const int m = ((wid + 8 * k) << 5) + lane;         // float4 idx 0..1023
        const float4 a = __ldcs(&rp4[m]);                  // own 4 sites

        // Up-neighbor chunk m+16: lanes 16-31 load it; lanes 0-15 get it
        // from lane+16's a via shfl_down.
        float4 bl = make_float4(0.f, 0.f, 0.f, 0.f);
        if (hi_half)
            bl = __ldcs(&rp4[(m + 16) & (LATTICE/4 - 1)]);
        const float sx = __shfl_down_sync(0xffffffffu, a.x, 16);
        const float sy = __shfl_down_sync(0xffffffffu, a.y, 16);
        const float sz = __shfl_down_sync(0xffffffffu, a.z, 16);
        const float sw = __shfl_down_sync(0xffffffffu, a.w, 16);
        float4 b;
        b.x = hi_half ? bl.x : sx;
        b.y = hi_half ? bl.y : sy;
        b.z = hi_half ? bl.z : sz;
        b.w = hi_half ? bl.w : sw;

        const float xr3 = __shfl_sync(0xffffffffu, a.x, src_lane);

        acc  += __cosf(b.x - a.x);   // up bonds
        acc  += __cosf(b.y - a.y);
        acc  += __cosf(b.z - a.z);
        acc  += __cosf(b.w - a.w);
        acc  += __cosf(a.y - a.x);   // right bonds
        accp += cos_poly(a.z - a.y); // FMA-pipe bond (MUFU relief)
        acc  += __cosf(a.w - a.z);
        acc  += __cosf(xr3 - a.w);
    }
    acc += accp;

    // Warp reduce
    #pragma unroll
    for (int o = 16; o > 0; o >>= 1)
        acc += __shfl_down_sync(0xffffffffu, acc, o);
    if (lane == 0)
        warp_sums[wid] = acc;
    __syncthreads();

    if (tid < 8) {
        float v = warp_sums[tid];
        #pragma unroll
        for (int o = 4; o > 0; o >>= 1)
            v += __shfl_down_sync(0x000000ffu, v, o);
        if (tid == 0)
            out[blockIdx.x] = v;
    }
}

extern "C" void kernel_launch(void* const* d_in, const int* in_sizes, int n_in,
                              void* d_out, int out_size)
{
    const float* state = (const float*)d_in[0];
    // d_in[1] (shift table, int64) is reproduced arithmetically in-kernel.
    float* out = (float*)d_out;

    const int n_samples = in_sizes[0] / LATTICE;  // 16384
    xy_hamiltonian_kernel<<<n_samples, THREADS>>>(state, out);
}

// round 10
// speedup vs baseline: 1.3049x; 1.3049x over previous
#include <cuda_runtime.h>

// XY model log-density: out[s] = sum_i cos(x[up(i)] - x[i]) + cos(x[right(i)] - x[i])
// 64x64 lattice (4096 sites), 16384 samples, BETA = 1.
//
// R10: R8 (best, at the bandwidth floor) with 512 threads/CTA instead of 256.
// Same access pattern (contiguous float4 a + (+16)-offset b, right bonds from
// registers + one shfl), half the per-thread body, half the launch waves.

#define LATTICE 4096
#define THREADS 512

// FMA-pipe cos for d in (-2pi,2pi): half-angle + even Taylor, err <= 4e-6.
__device__ __forceinline__ float cos_poly(float d)
{
    const float y = 0.5f * d;
    const float u = y * y;
    float p = -1.1470746e-11f;
    p = fmaf(p, u,  2.0876757e-9f);
    p = fmaf(p, u, -2.7557319e-7f);
    p = fmaf(p, u,  2.4801587e-5f);
    p = fmaf(p, u, -1.3888889e-3f);
    p = fmaf(p, u,  4.1666668e-2f);
    p = fmaf(p, u, -0.5f);
    p = fmaf(p, u,  1.0f);              // p = cos(y)
    return fmaf(p + p, p, -1.0f);       // 2p^2 - 1
}

__global__ __launch_bounds__(THREADS) void xy_hamiltonian_kernel(
    const float* __restrict__ state,
    float* __restrict__ out)
{
    __shared__ float warp_sums[THREADS / 32];

    const int tid  = threadIdx.x;
    const int lane = tid & 31;
    const float4* __restrict__ rp4 =
        reinterpret_cast<const float4*>(state + (size_t)blockIdx.x * LATTICE);

    // Right-neighbor source lane: within each 16-lane group (one 64-site
    // lattice row = 16 float4), lane L's boundary right-neighbor is lane
    // L+1's a.x, wrapping to the group's first lane at col 63.
    const int src_lane = (lane & ~15) | ((lane + 1) & 15);

    float acc  = 0.0f;
    float accp = 0.0f;
    #pragma unroll
    for (int k = 0; k < 2; k++) {
        const int m = tid + k * THREADS;                           // float4 idx 0..1023
        const float4 a = __ldcs(&rp4[m]);                          // own sites
        const float4 b = __ldcs(&rp4[(m + 16) & (LATTICE/4 - 1)]); // up neighbors (+64, periodic)
        const float xr3 = __shfl_sync(0xffffffffu, a.x, src_lane);

        acc  += __cosf(b.x - a.x);   // up bonds (MUFU)
        acc  += __cosf(b.y - a.y);
        acc  += __cosf(b.z - a.z);
        acc  += __cosf(b.w - a.w);
        acc  += __cosf(a.y - a.x);   // right bonds
        accp += cos_poly(a.z - a.y); // FMA-pipe bond (MUFU relief)
        acc  += __cosf(a.w - a.z);
        acc  += __cosf(xr3 - a.w);
    }
    acc += accp;

    // Warp reduce
    #pragma unroll
    for (int o = 16; o > 0; o >>= 1)
        acc += __shfl_down_sync(0xffffffffu, acc, o);
    if (lane == 0)
        warp_sums[tid >> 5] = acc;
    __syncthreads();

    // Final reduce across 16 warps
    if (tid < 16) {
        float v = warp_sums[tid];
        #pragma unroll
        for (int o = 8; o > 0; o >>= 1)
            v += __shfl_down_sync(0x0000ffffu, v, o);
        if (tid == 0)
            out[blockIdx.x] = v;
    }
}

extern "C" void kernel_launch(void* const* d_in, const int* in_sizes, int n_in,
                              void* d_out, int out_size)
{
    const float* state = (const float*)d_in[0];
    // d_in[1] (shift table, int64) is reproduced arithmetically in-kernel.
    float* out = (float*)d_out;

    const int n_samples = in_sizes[0] / LATTICE;  // 16384
    xy_hamiltonian_kernel<<<n_samples, THREADS>>>(state, out);
}